// round 11
// baseline (speedup 1.0000x reference)
#include <cuda_runtime.h>
#include <math.h>

#define NN 2048
#define BB 8

// ---------------- scratch (static device allocations) ----------------
__device__ float g_PL[BB * 15 * NN];                 // left projections  [b][ct][row]
__device__ float g_PR[BB * 15 * NN];                 // right projections [b][ct][col]
__device__ float g_LR[BB * 2 * NN];                  // sigmoid outputs: [b][0]=left, [b][1]=right
__device__ float g_dsum[64 * BB];                    // per-(d,b) band sums

// ---------------- packed f32x2 helpers ----------------
__device__ __forceinline__ unsigned long long pack2(float lo, float hi) {
    unsigned long long r;
    asm("mov.b64 %0, {%1, %2};" : "=l"(r) : "f"(lo), "f"(hi));
    return r;
}
__device__ __forceinline__ void fma2(unsigned long long& d, unsigned long long a,
                                     unsigned long long b) {
    asm("fma.rn.f32x2 %0, %1, %2, %0;" : "+l"(d) : "l"(a), "l"(b));
}
__device__ __forceinline__ float hadd2(unsigned long long v) {
    float lo, hi;
    asm("mov.b64 {%0, %1}, %2;" : "=f"(lo), "=f"(hi) : "l"(v));
    return lo + hi;
}
__device__ __forceinline__ float2 unpk(unsigned long long v) {
    float lo, hi;
    asm("mov.b64 {%0, %1}, %2;" : "=f"(lo), "=f"(hi) : "l"(v));
    return make_float2(lo, hi);
}

// ---------------- fused projection kernel (latency-hidden staging + x prefetch) ----------------
// 1280 blocks: t%5==0 -> PR (256), else PL (1024).
__global__ __launch_bounds__(256) void proj_kernel(const float* __restrict__ x,
                                                   const float* __restrict__ wl,
                                                   const float* __restrict__ wr) {
    __shared__ __align__(16) char smem_raw[30720];
    int tid = threadIdx.x;
    int t = blockIdx.x;

    if (t % 5 == 0) {
        // ================= PR path =================
        int pr_idx = t / 5;                                         // 0..255
        unsigned long long (*ws)[4][32][15] =
            (unsigned long long(*)[4][32][15])smem_raw;             // 2 x 15360 B
        float2 (*racc)[64][15] = (float2(*)[64][15])smem_raw;       // aliases ws (post-loop)

        int b = pr_idx >> 5;
        int stripe = pr_idx & 31;
        int colloc = tid & 63;
        int seg = tid >> 6;                  // 0..3
        int col = stripe * 64 + colloc;
        const float* xb = x + (size_t)b * NN * NN + col;

        unsigned long long acc[15];
#pragma unroll
        for (int ct = 0; ct < 15; ++ct) acc[ct] = 0ull;

        // prologue: stage chunk 0 weights directly
        for (int i = tid; i < 1920; i += 256) {
            int s = i / 480, rem = i % 480;
            int hp = rem / 15, ct = rem % 15;
            int h = s * 512 + hp * 2;
            int c = ct / 3, tt = ct % 3;
            ws[0][s][hp][ct] = pack2(wr[((size_t)c * NN + h) * 3 + tt],
                                     wr[((size_t)c * NN + h + 1) * 3 + tt]);
        }
        __syncthreads();

#pragma unroll 1
        for (int chunk = 0; chunk < 8; ++chunk) {
            int buf = chunk & 1;
            // 1) issue next-chunk weight LDGs into registers (latency hidden under FMAs)
            unsigned long long stg[8];
#pragma unroll
            for (int j = 0; j < 8; ++j) {
                int i = tid + j * 256;
                if (chunk < 7 && i < 1920) {
                    int s = i / 480, rem = i % 480;
                    int hp = rem / 15, ct = rem % 15;
                    int h = s * 512 + (chunk + 1) * 64 + hp * 2;
                    int c = ct / 3, tt = ct % 3;
                    stg[j] = pack2(wr[((size_t)c * NN + h) * 3 + tt],
                                   wr[((size_t)c * NN + h + 1) * 3 + tt]);
                }
            }
            // 2) compute with x double-buffered in registers (MLP 16)
            const float* xp = xb + (size_t)(seg * 512 + chunk * 64) * NN;
            float xv[2][16];
#pragma unroll
            for (int i = 0; i < 16; ++i) xv[0][i] = xp[(size_t)i * NN];
#pragma unroll
            for (int grp = 0; grp < 4; ++grp) {
                int cur = grp & 1, nxt = cur ^ 1;
                if (grp < 3) {
#pragma unroll
                    for (int i = 0; i < 16; ++i)
                        xv[nxt][i] = xp[(size_t)(16 * (grp + 1) + i) * NN];
                }
#pragma unroll
                for (int hp = 0; hp < 8; ++hp) {
                    unsigned long long xvp = pack2(xv[cur][2 * hp], xv[cur][2 * hp + 1]);
#pragma unroll
                    for (int ct = 0; ct < 15; ++ct)
                        fma2(acc[ct], xvp, ws[buf][seg][grp * 8 + hp][ct]);
                }
            }
            // 3) commit staged weights to the other buffer, then sync
            if (chunk < 7) {
#pragma unroll
                for (int j = 0; j < 8; ++j) {
                    int i = tid + j * 256;
                    if (i < 1920) {
                        int s = i / 480, rem = i % 480;
                        int hp = rem / 15, ct = rem % 15;
                        ws[buf ^ 1][s][hp][ct] = stg[j];
                    }
                }
            }
            __syncthreads();
        }

        // cross-seg reduce (racc aliases ws; all ws reads done at final sync)
        if (seg > 0) {
#pragma unroll
            for (int ct = 0; ct < 15; ++ct) racc[seg - 1][colloc][ct] = unpk(acc[ct]);
        }
        __syncthreads();
        if (seg == 0) {
#pragma unroll
            for (int ct = 0; ct < 15; ++ct) {
                float v = hadd2(acc[ct]);
#pragma unroll
                for (int s = 0; s < 3; ++s) {
                    float2 r = racc[s][colloc][ct];
                    v += r.x + r.y;
                }
                g_PR[((size_t)b * 15 + ct) * NN + col] = v;
            }
        }
    } else {
        // ================= PL path (2 rows/warp, x + staging prefetch) =================
        int pl_idx = (t / 5) * 4 + (t % 5) - 1;                     // 0..1023
        float4 (*sw)[480] = (float4(*)[480])smem_raw;               // 2 x 7680 B

        int warp = tid >> 5, lane = tid & 31;
        int g = pl_idx * 8 + warp;           // 0..8191
        int b = g >> 10;
        int r0 = (g & 1023) << 1;            // 2 rows per warp
        const float* xb = x + (size_t)b * NN * NN + (size_t)r0 * NN;
        const float4* wl4 = (const float4*)wl;   // [ct][512] float4

        float acc[2][15];
#pragma unroll
        for (int r = 0; r < 2; r++)
#pragma unroll
            for (int c = 0; c < 15; c++) acc[r][c] = 0.f;

        // prologue: stage chunk 0 weights; prefetch k=0 x
        for (int i = tid; i < 480; i += 256) {
            int ct = i >> 5, j = i & 31;
            sw[0][ct * 32 + j] = wl4[ct * 512 + j];
        }
        float4 nx0 = *(const float4*)(xb + 0 * NN + lane * 4);
        float4 nx1 = *(const float4*)(xb + 1 * NN + lane * 4);
        __syncthreads();

#pragma unroll 1
        for (int k = 0; k < 16; ++k) {
            int buf = k & 1;
            float4 cur0 = nx0, cur1 = nx1;
            float4 stg0, stg1;
            if (k < 15) {
                // issue next-iter LDGs now; consume after the FMA burst
                int w = (k + 1) * 128 + lane * 4;
                nx0 = *(const float4*)(xb + 0 * NN + w);
                nx1 = *(const float4*)(xb + 1 * NN + w);
                {
                    int ct = tid >> 5, j = tid & 31;
                    stg0 = wl4[ct * 512 + (k + 1) * 32 + j];
                }
                if (tid < 224) {
                    int i2 = tid + 256;
                    int ct = i2 >> 5, j = i2 & 31;
                    stg1 = wl4[ct * 512 + (k + 1) * 32 + j];
                }
            }
#pragma unroll
            for (int ct = 0; ct < 15; ++ct) {
                float4 wv = sw[buf][ct * 32 + lane];
                acc[0][ct] = fmaf(cur0.x, wv.x, acc[0][ct]);
                acc[0][ct] = fmaf(cur0.y, wv.y, acc[0][ct]);
                acc[0][ct] = fmaf(cur0.z, wv.z, acc[0][ct]);
                acc[0][ct] = fmaf(cur0.w, wv.w, acc[0][ct]);
                acc[1][ct] = fmaf(cur1.x, wv.x, acc[1][ct]);
                acc[1][ct] = fmaf(cur1.y, wv.y, acc[1][ct]);
                acc[1][ct] = fmaf(cur1.z, wv.z, acc[1][ct]);
                acc[1][ct] = fmaf(cur1.w, wv.w, acc[1][ct]);
            }
            if (k < 15) {
                {
                    int ct = tid >> 5, j = tid & 31;
                    sw[buf ^ 1][ct * 32 + j] = stg0;
                }
                if (tid < 224) {
                    int i2 = tid + 256;
                    int ct = i2 >> 5, j = i2 & 31;
                    sw[buf ^ 1][ct * 32 + j] = stg1;
                }
            }
            __syncthreads();
        }

#pragma unroll
        for (int r = 0; r < 2; r++) {
#pragma unroll
            for (int ct = 0; ct < 15; ++ct) {
                float v = acc[r][ct];
                v += __shfl_down_sync(0xffffffffu, v, 16);
                v += __shfl_down_sync(0xffffffffu, v, 8);
                v += __shfl_down_sync(0xffffffffu, v, 4);
                v += __shfl_down_sync(0xffffffffu, v, 2);
                v += __shfl_down_sync(0xffffffffu, v, 1);
                if (lane == 0) g_PL[((size_t)b * 15 + ct) * NN + r0 + r] = v;
            }
        }
    }
}

// ---------------- kernel 4: fused conv stack + sigmoid ----------------
#define TW 64
#define NT (NN / TW)          // 32 tiles
#define HALO 6
#define W2 (TW + 2 * HALO)    // 76
__global__ __launch_bounds__(256) void conv_kernel(
    const float* __restrict__ bl, const float* __restrict__ br,
    const float* __restrict__ wA, const float* __restrict__ bA,
    const float* __restrict__ wB, const float* __restrict__ bB,
    const float* __restrict__ wT, const float* __restrict__ bT,
    const float* __restrict__ wm, const float* __restrict__ bm) {
    __shared__ float hbuf[2][10][W2];
    __shared__ float sA[300], sB[300], sT[300];
    __shared__ float swm[20], sbA[10], sbB[10], sbT[10], sbm[2];

    int tid = threadIdx.x;
    int b = blockIdx.x / NT;
    int p0 = (blockIdx.x % NT) * TW;

    for (int i = tid; i < 300; i += 256) {
        sA[i] = wA[i];
        sB[i] = wB[i];
        int o = i / 30, ii = (i / 3) % 10, t = i % 3;
        sT[i] = wT[(ii * 10 + o) * 3 + (2 - t)];   // wTc[o][ii][t] = wT[ii][o][2-t]
    }
    if (tid < 20) swm[tid] = wm[tid];
    if (tid < 10) { sbA[tid] = bA[tid]; sbB[tid] = bB[tid]; sbT[tid] = bT[tid]; }
    if (tid < 2) sbm[tid] = bm[tid];

    // build lr (with halo) from projections + 3-tap shift + bias
    for (int i = tid; i < 10 * W2; i += 256) {
        int ch = i / W2, pl = i % W2;
        int gp = p0 - HALO + pl;
        float v = 0.f;
        if (gp >= 0 && gp < NN) {
            if (ch < 5) {
                v = bl[ch];
#pragma unroll
                for (int t = 0; t < 3; t++) {
                    int ri = gp - 1 + t;
                    if (ri >= 0 && ri < NN) v += g_PL[((size_t)b * 15 + ch * 3 + t) * NN + ri];
                }
            } else {
                int c = ch - 5;
                v = br[c];
#pragma unroll
                for (int t = 0; t < 3; t++) {
                    int ci = gp - 1 + t;
                    if (ci >= 0 && ci < NN) v += g_PR[((size_t)b * 15 + c * 3 + t) * NN + ci];
                }
            }
        }
        hbuf[0][ch][pl] = v;
    }
    __syncthreads();

    int src = 0;
#pragma unroll 1
    for (int layer = 0; layer < 6; ++layer) {
        const float* W = (layer == 0) ? sA : ((layer < 3) ? sB : sT);
        const float* bias = (layer == 0) ? sbA : ((layer < 3) ? sbB : sbT);
        int dst = src ^ 1;
        for (int i = tid; i < 10 * W2; i += 256) {
            int o = i / W2, p = i % W2;
            float s = bias[o];
#pragma unroll
            for (int ci = 0; ci < 10; ++ci) {
                float a0 = (p > 0) ? hbuf[src][ci][p - 1] : 0.f;
                float a1 = hbuf[src][ci][p];
                float a2 = (p < W2 - 1) ? hbuf[src][ci][p + 1] : 0.f;
                const float* w3 = W + (o * 10 + ci) * 3;
                s = fmaf(a0, w3[0], s);
                s = fmaf(a1, w3[1], s);
                s = fmaf(a2, w3[2], s);
            }
            hbuf[dst][o][p] = fmaxf(s, 0.f);
        }
        __syncthreads();
        src = dst;
    }

    // pointwise wm + sigmoid -> left/right
    for (int i = tid; i < 2 * TW; i += 256) {
        int sch = i / TW;
        int pl = i % TW;
        int p = HALO + pl;
        float z = sbm[sch];
#pragma unroll
        for (int ci = 0; ci < 10; ++ci) z = fmaf(hbuf[src][ci][p], swm[sch * 10 + ci], z);
        g_LR[((size_t)b * 2 + sch) * NN + p0 + pl] = 1.f / (1.f + expf(-z));
    }
}

// ---------------- kernel 5: diagonal-band predictions (raw p + per-(d,b) sums) ----------------
__global__ __launch_bounds__(256) void preds_kernel(const float* __restrict__ x,
                                                    float* __restrict__ out) {
    __shared__ float red[8];
    int b = blockIdx.x >> 6;
    int d = (blockIdx.x & 63) + 1;
    int L = NN - d - 1;
    const float* xb = x + (size_t)b * NN * NN;
    const float* left = g_LR + (size_t)b * 2 * NN;
    const float* right = left + NN;
    int tid = threadIdx.x;

    size_t base = (size_t)b * 128928 + (size_t)(d - 1) * 2047 - (size_t)((d - 1) * d / 2);

    float lsum = 0.f;
    for (int j = tid; j < L; j += 256) {
        float c0 = expf(xb[(size_t)j * NN + j + d]);
        float c1 = expf(xb[(size_t)(j + 1) * NN + (j + 1) + d]);
        float mi = c1 * right[j + 1] + c0 * left[d + j];
        float mo = right[j] + left[d + 1 + j];
        float p = logf(mi / mo);
        out[base + j] = p;
        lsum += p;
    }
    lsum += __shfl_down_sync(0xffffffffu, lsum, 16);
    lsum += __shfl_down_sync(0xffffffffu, lsum, 8);
    lsum += __shfl_down_sync(0xffffffffu, lsum, 4);
    lsum += __shfl_down_sync(0xffffffffu, lsum, 2);
    lsum += __shfl_down_sync(0xffffffffu, lsum, 1);
    if ((tid & 31) == 0) red[tid >> 5] = lsum;
    __syncthreads();
    if (tid == 0) {
        float t = 0.f;
#pragma unroll
        for (int i = 0; i < 8; i++) t += red[i];
        g_dsum[(d - 1) * BB + b] = t;
    }
}

// ---------------- kernel 6: subtract global (over batches) mean per band ----------------
__global__ __launch_bounds__(256) void meansub_kernel(float* __restrict__ out) {
    int dd = blockIdx.x >> 3;          // 0..63
    int b = blockIdx.x & 7;
    int d = dd + 1;
    int L = NN - d - 1;
    float s = 0.f;
#pragma unroll
    for (int i = 0; i < 8; i++) s += g_dsum[dd * BB + i];
    float mean = s / (float)(BB * L);
    size_t base = (size_t)b * 128928 + (size_t)(d - 1) * 2047 - (size_t)((d - 1) * d / 2);
    for (int j = threadIdx.x; j < L; j += 256) out[base + j] -= mean;
}

// ---------------- launch ----------------
extern "C" void kernel_launch(void* const* d_in, const int* in_sizes, int n_in,
                              void* d_out, int out_size) {
    const float* x  = (const float*)d_in[0];
    const float* wl = (const float*)d_in[1];
    const float* bl = (const float*)d_in[2];
    const float* wr = (const float*)d_in[3];
    const float* br = (const float*)d_in[4];
    const float* wA = (const float*)d_in[5];
    const float* bA = (const float*)d_in[6];
    const float* wB = (const float*)d_in[7];
    const float* bB = (const float*)d_in[8];
    const float* wT = (const float*)d_in[9];
    const float* bT = (const float*)d_in[10];
    const float* wm = (const float*)d_in[11];
    const float* bm = (const float*)d_in[12];
    float* out = (float*)d_out;

    proj_kernel<<<1280, 256>>>(x, wl, wr);
    conv_kernel<<<8 * NT, 256>>>(bl, br, wA, bA, wB, bB, wT, bT, wm, bm);
    preds_kernel<<<512, 256>>>(x, out);
    meansub_kernel<<<512, 256>>>(out);
}

// round 12
// speedup vs baseline: 1.2309x; 1.2309x over previous
#include <cuda_runtime.h>
#include <math.h>

#define NN 2048
#define BB 8

// ---------------- scratch (static device allocations) ----------------
__device__ float g_PL[BB * 15 * NN];                 // left projections  [b][ct][row]
__device__ float g_PR[BB * 15 * NN];                 // right projections [b][ct][col]
__device__ float g_LR[BB * 2 * NN];                  // sigmoid outputs: [b][0]=left, [b][1]=right
__device__ float g_dsum[64 * BB];                    // per-(d,b) band sums

// ---------------- packed f32x2 helpers ----------------
__device__ __forceinline__ unsigned long long pack2(float lo, float hi) {
    unsigned long long r;
    asm("mov.b64 %0, {%1, %2};" : "=l"(r) : "f"(lo), "f"(hi));
    return r;
}
__device__ __forceinline__ void fma2(unsigned long long& d, unsigned long long a,
                                     unsigned long long b) {
    asm("fma.rn.f32x2 %0, %1, %2, %0;" : "+l"(d) : "l"(a), "l"(b));
}
__device__ __forceinline__ float hadd2(unsigned long long v) {
    float lo, hi;
    asm("mov.b64 {%0, %1}, %2;" : "=f"(lo), "=f"(hi) : "l"(v));
    return lo + hi;
}
__device__ __forceinline__ float2 unpk(unsigned long long v) {
    float lo, hi;
    asm("mov.b64 {%0, %1}, %2;" : "=f"(lo), "=f"(hi) : "l"(v));
    return make_float2(lo, hi);
}

// ---------------- dummy kernels (profiler slot alignment) ----------------
__global__ void dummy_kernel() {}

// ---------------- fused projection kernel (R10 structure; __ldcs on x) ----------------
// 1280 blocks: t%5==0 -> PR block (256 total), else PL block (1024 total).
__global__ __launch_bounds__(256) void proj_kernel(const float* __restrict__ x,
                                                   const float* __restrict__ wl,
                                                   const float* __restrict__ wr) {
    __shared__ __align__(16) char smem_raw[30720];
    int tid = threadIdx.x;
    int t = blockIdx.x;

    if (t % 5 == 0) {
        // ================= PR path =================
        int pr_idx = t / 5;                                         // 0..255
        unsigned long long (*ws)[4][32][15] =
            (unsigned long long(*)[4][32][15])smem_raw;             // 2 x 15360 B
        float2 (*racc)[64][15] = (float2(*)[64][15])smem_raw;       // aliases ws (post-loop)

        int b = pr_idx >> 5;
        int stripe = pr_idx & 31;
        int colloc = tid & 63;
        int seg = tid >> 6;                  // 0..3
        int col = stripe * 64 + colloc;
        const float* xb = x + (size_t)b * NN * NN + col;

        unsigned long long acc[15];
#pragma unroll
        for (int ct = 0; ct < 15; ++ct) acc[ct] = 0ull;

        // stage chunk 0 into buffer 0
        for (int i = tid; i < 1920; i += 256) {
            int s = i / 480, rem = i % 480;
            int hp = rem / 15, ct = rem % 15;
            int h = s * 512 + hp * 2;
            int c = ct / 3, tt = ct % 3;
            ws[0][s][hp][ct] = pack2(wr[((size_t)c * NN + h) * 3 + tt],
                                     wr[((size_t)c * NN + h + 1) * 3 + tt]);
        }
        __syncthreads();

#pragma unroll 1
        for (int chunk = 0; chunk < 8; ++chunk) {
            int buf = chunk & 1;
            if (chunk < 7) {
                for (int i = tid; i < 1920; i += 256) {
                    int s = i / 480, rem = i % 480;
                    int hp = rem / 15, ct = rem % 15;
                    int h = s * 512 + (chunk + 1) * 64 + hp * 2;
                    int c = ct / 3, tt = ct % 3;
                    ws[buf ^ 1][s][hp][ct] =
                        pack2(wr[((size_t)c * NN + h) * 3 + tt],
                              wr[((size_t)c * NN + h + 1) * 3 + tt]);
                }
            }
            int hbase = seg * 512 + chunk * 64;
            const float* xp = xb + (size_t)hbase * NN;
#pragma unroll 4
            for (int hp = 0; hp < 32; ++hp) {
                float x0 = __ldcs(xp + (size_t)(2 * hp) * NN);
                float x1 = __ldcs(xp + (size_t)(2 * hp + 1) * NN);
                unsigned long long xv = pack2(x0, x1);
#pragma unroll
                for (int ct = 0; ct < 15; ++ct) fma2(acc[ct], xv, ws[buf][seg][hp][ct]);
            }
            __syncthreads();
        }

        // cross-seg reduce (racc aliases ws; all ws reads completed at loop-end sync)
        if (seg > 0) {
#pragma unroll
            for (int ct = 0; ct < 15; ++ct) racc[seg - 1][colloc][ct] = unpk(acc[ct]);
        }
        __syncthreads();
        if (seg == 0) {
#pragma unroll
            for (int ct = 0; ct < 15; ++ct) {
                float v = hadd2(acc[ct]);
#pragma unroll
                for (int s = 0; s < 3; ++s) {
                    float2 r = racc[s][colloc][ct];
                    v += r.x + r.y;
                }
                g_PR[((size_t)b * 15 + ct) * NN + col] = v;
            }
        }
    } else {
        // ================= PL path (2 rows per warp, scalar FFMA) =================
        int pl_idx = (t / 5) * 4 + (t % 5) - 1;                     // 0..1023
        float4 (*sw)[480] = (float4(*)[480])smem_raw;               // 2 x 7680 B

        int warp = tid >> 5, lane = tid & 31;
        int g = pl_idx * 8 + warp;           // 0..8191
        int b = g >> 10;                     // 1024 warp-groups per batch
        int r0 = (g & 1023) << 1;            // 2 rows per warp
        const float* xb = x + (size_t)b * NN * NN + (size_t)r0 * NN;
        const float4* wl4 = (const float4*)wl;   // [ct][512] float4

        float acc[2][15];
#pragma unroll
        for (int r = 0; r < 2; r++)
#pragma unroll
            for (int c = 0; c < 15; c++) acc[r][c] = 0.f;

        // stage chunk 0
        for (int i = tid; i < 480; i += 256) {
            int ct = i >> 5, j = i & 31;
            sw[0][ct * 32 + j] = wl4[ct * 512 + j];
        }
        __syncthreads();

#pragma unroll 1
        for (int k = 0; k < 16; ++k) {
            int buf = k & 1;
            if (k < 15) {
                for (int i = tid; i < 480; i += 256) {
                    int ct = i >> 5, j = i & 31;
                    sw[buf ^ 1][ct * 32 + j] = wl4[ct * 512 + (k + 1) * 32 + j];
                }
            }
            int w = k * 128 + lane * 4;
            float4 xv0 = __ldcs((const float4*)(xb + 0 * NN + w));
            float4 xv1 = __ldcs((const float4*)(xb + 1 * NN + w));
#pragma unroll
            for (int ct = 0; ct < 15; ++ct) {
                float4 wv = sw[buf][ct * 32 + lane];
                acc[0][ct] = fmaf(xv0.x, wv.x, acc[0][ct]);
                acc[0][ct] = fmaf(xv0.y, wv.y, acc[0][ct]);
                acc[0][ct] = fmaf(xv0.z, wv.z, acc[0][ct]);
                acc[0][ct] = fmaf(xv0.w, wv.w, acc[0][ct]);
                acc[1][ct] = fmaf(xv1.x, wv.x, acc[1][ct]);
                acc[1][ct] = fmaf(xv1.y, wv.y, acc[1][ct]);
                acc[1][ct] = fmaf(xv1.z, wv.z, acc[1][ct]);
                acc[1][ct] = fmaf(xv1.w, wv.w, acc[1][ct]);
            }
            __syncthreads();
        }

#pragma unroll
        for (int r = 0; r < 2; r++) {
#pragma unroll
            for (int ct = 0; ct < 15; ++ct) {
                float v = acc[r][ct];
                v += __shfl_down_sync(0xffffffffu, v, 16);
                v += __shfl_down_sync(0xffffffffu, v, 8);
                v += __shfl_down_sync(0xffffffffu, v, 4);
                v += __shfl_down_sync(0xffffffffu, v, 2);
                v += __shfl_down_sync(0xffffffffu, v, 1);
                if (lane == 0) g_PL[((size_t)b * 15 + ct) * NN + r0 + r] = v;
            }
        }
    }
}

// ---------------- kernel 4: fused conv stack + sigmoid ----------------
#define TW 64
#define NT (NN / TW)          // 32 tiles
#define HALO 6
#define W2 (TW + 2 * HALO)    // 76
__global__ __launch_bounds__(256) void conv_kernel(
    const float* __restrict__ bl, const float* __restrict__ br,
    const float* __restrict__ wA, const float* __restrict__ bA,
    const float* __restrict__ wB, const float* __restrict__ bB,
    const float* __restrict__ wT, const float* __restrict__ bT,
    const float* __restrict__ wm, const float* __restrict__ bm) {
    __shared__ float hbuf[2][10][W2];
    __shared__ float sA[300], sB[300], sT[300];
    __shared__ float swm[20], sbA[10], sbB[10], sbT[10], sbm[2];

    int tid = threadIdx.x;
    int b = blockIdx.x / NT;
    int p0 = (blockIdx.x % NT) * TW;

    for (int i = tid; i < 300; i += 256) {
        sA[i] = wA[i];
        sB[i] = wB[i];
        int o = i / 30, ii = (i / 3) % 10, t = i % 3;
        sT[i] = wT[(ii * 10 + o) * 3 + (2 - t)];   // wTc[o][ii][t] = wT[ii][o][2-t]
    }
    if (tid < 20) swm[tid] = wm[tid];
    if (tid < 10) { sbA[tid] = bA[tid]; sbB[tid] = bB[tid]; sbT[tid] = bT[tid]; }
    if (tid < 2) sbm[tid] = bm[tid];

    // build lr (with halo) from projections + 3-tap shift + bias
    for (int i = tid; i < 10 * W2; i += 256) {
        int ch = i / W2, pl = i % W2;
        int gp = p0 - HALO + pl;
        float v = 0.f;
        if (gp >= 0 && gp < NN) {
            if (ch < 5) {
                v = bl[ch];
#pragma unroll
                for (int t = 0; t < 3; t++) {
                    int ri = gp - 1 + t;
                    if (ri >= 0 && ri < NN) v += g_PL[((size_t)b * 15 + ch * 3 + t) * NN + ri];
                }
            } else {
                int c = ch - 5;
                v = br[c];
#pragma unroll
                for (int t = 0; t < 3; t++) {
                    int ci = gp - 1 + t;
                    if (ci >= 0 && ci < NN) v += g_PR[((size_t)b * 15 + c * 3 + t) * NN + ci];
                }
            }
        }
        hbuf[0][ch][pl] = v;
    }
    __syncthreads();

    int src = 0;
#pragma unroll 1
    for (int layer = 0; layer < 6; ++layer) {
        const float* W = (layer == 0) ? sA : ((layer < 3) ? sB : sT);
        const float* bias = (layer == 0) ? sbA : ((layer < 3) ? sbB : sbT);
        int dst = src ^ 1;
        for (int i = tid; i < 10 * W2; i += 256) {
            int o = i / W2, p = i % W2;
            float s = bias[o];
#pragma unroll
            for (int ci = 0; ci < 10; ++ci) {
                float a0 = (p > 0) ? hbuf[src][ci][p - 1] : 0.f;
                float a1 = hbuf[src][ci][p];
                float a2 = (p < W2 - 1) ? hbuf[src][ci][p + 1] : 0.f;
                const float* w3 = W + (o * 10 + ci) * 3;
                s = fmaf(a0, w3[0], s);
                s = fmaf(a1, w3[1], s);
                s = fmaf(a2, w3[2], s);
            }
            hbuf[dst][o][p] = fmaxf(s, 0.f);
        }
        __syncthreads();
        src = dst;
    }

    // pointwise wm + sigmoid -> left/right
    for (int i = tid; i < 2 * TW; i += 256) {
        int sch = i / TW;
        int pl = i % TW;
        int p = HALO + pl;
        float z = sbm[sch];
#pragma unroll
        for (int ci = 0; ci < 10; ++ci) z = fmaf(hbuf[src][ci][p], swm[sch * 10 + ci], z);
        g_LR[((size_t)b * 2 + sch) * NN + p0 + pl] = 1.f / (1.f + expf(-z));
    }
}

// ---------------- kernel 5: diagonal-band predictions (raw p + per-(d,b) sums) ----------------
__global__ __launch_bounds__(256) void preds_kernel(const float* __restrict__ x,
                                                    float* __restrict__ out) {
    __shared__ float red[8];
    int b = blockIdx.x >> 6;
    int d = (blockIdx.x & 63) + 1;
    int L = NN - d - 1;
    const float* xb = x + (size_t)b * NN * NN;
    const float* left = g_LR + (size_t)b * 2 * NN;
    const float* right = left + NN;
    int tid = threadIdx.x;

    size_t base = (size_t)b * 128928 + (size_t)(d - 1) * 2047 - (size_t)((d - 1) * d / 2);

    float lsum = 0.f;
    for (int j = tid; j < L; j += 256) {
        float c0 = expf(__ldcs(xb + (size_t)j * NN + j + d));
        float c1 = expf(__ldcs(xb + (size_t)(j + 1) * NN + (j + 1) + d));
        float mi = c1 * right[j + 1] + c0 * left[d + j];
        float mo = right[j] + left[d + 1 + j];
        float p = logf(mi / mo);
        out[base + j] = p;
        lsum += p;
    }
    lsum += __shfl_down_sync(0xffffffffu, lsum, 16);
    lsum += __shfl_down_sync(0xffffffffu, lsum, 8);
    lsum += __shfl_down_sync(0xffffffffu, lsum, 4);
    lsum += __shfl_down_sync(0xffffffffu, lsum, 2);
    lsum += __shfl_down_sync(0xffffffffu, lsum, 1);
    if ((tid & 31) == 0) red[tid >> 5] = lsum;
    __syncthreads();
    if (tid == 0) {
        float t = 0.f;
#pragma unroll
        for (int i = 0; i < 8; i++) t += red[i];
        g_dsum[(d - 1) * BB + b] = t;
    }
}

// ---------------- kernel 6: subtract global (over batches) mean per band ----------------
__global__ __launch_bounds__(256) void meansub_kernel(float* __restrict__ out) {
    int dd = blockIdx.x >> 3;          // 0..63
    int b = blockIdx.x & 7;
    int d = dd + 1;
    int L = NN - d - 1;
    float s = 0.f;
#pragma unroll
    for (int i = 0; i < 8; i++) s += g_dsum[dd * BB + i];
    float mean = s / (float)(BB * L);
    size_t base = (size_t)b * 128928 + (size_t)(d - 1) * 2047 - (size_t)((d - 1) * d / 2);
    float* p = out + base;

    // align to 16B
    int head = (int)(((16 - ((size_t)p & 15)) & 15) >> 2);
    if (head > L) head = L;
    for (int j = threadIdx.x; j < head; j += 256) p[j] -= mean;
    int Lv = (L - head) >> 2;            // float4 count
    float4* pv = (float4*)(p + head);
    for (int j = threadIdx.x; j < Lv; j += 256) {
        float4 v = pv[j];
        v.x -= mean; v.y -= mean; v.z -= mean; v.w -= mean;
        pv[j] = v;
    }
    for (int j = head + (Lv << 2) + threadIdx.x; j < L; j += 256) p[j] -= mean;
}

// ---------------- launch ----------------
extern "C" void kernel_launch(void* const* d_in, const int* in_sizes, int n_in,
                              void* d_out, int out_size) {
    const float* x  = (const float*)d_in[0];
    const float* wl = (const float*)d_in[1];
    const float* bl = (const float*)d_in[2];
    const float* wr = (const float*)d_in[3];
    const float* br = (const float*)d_in[4];
    const float* wA = (const float*)d_in[5];
    const float* bA = (const float*)d_in[6];
    const float* wB = (const float*)d_in[7];
    const float* bB = (const float*)d_in[8];
    const float* wT = (const float*)d_in[9];
    const float* bT = (const float*)d_in[10];
    const float* wm = (const float*)d_in[11];
    const float* bm = (const float*)d_in[12];
    float* out = (float*)d_out;

    // 3 dummies so proj_kernel lands in the profiled (4th) launch slot
    dummy_kernel<<<1, 32>>>();
    dummy_kernel<<<1, 32>>>();
    dummy_kernel<<<1, 32>>>();
    proj_kernel<<<1280, 256>>>(x, wl, wr);
    conv_kernel<<<8 * NT, 256>>>(bl, br, wA, bA, wB, bB, wT, bT, wm, bm);
    preds_kernel<<<512, 256>>>(x, out);
    meansub_kernel<<<512, 256>>>(out);
}